// round 3
// baseline (speedup 1.0000x reference)
#include <cuda_runtime.h>

#define NTHR 128

__device__ __forceinline__ float2 ffma2(float2 a, float2 b, float2 c) {
    float2 d;
    asm("fma.rn.f32x2 %0, %1, %2, %3;"
        : "=l"(reinterpret_cast<unsigned long long&>(d))
        : "l"(reinterpret_cast<unsigned long long&>(a)),
          "l"(reinterpret_cast<unsigned long long&>(b)),
          "l"(reinterpret_cast<unsigned long long&>(c)));
    return d;
}

// epilogue for one position-pair: max/min trees + equality histogram
__device__ __forceinline__ void epi_pair(const float2 z[8], int gpos0, int nPos,
                                         float cmax[8], unsigned& clo, unsigned& chi)
{
#pragma unroll
    for (int s = 0; s < 2; s++) {
        float v[8];
#pragma unroll
        for (int k = 0; k < 8; k++) v[k] = s ? z[k].y : z[k].x;
        float m = fmaxf(fmaxf(fmaxf(v[0], v[1]), fmaxf(v[2], v[3])),
                        fmaxf(fmaxf(v[4], v[5]), fmaxf(v[6], v[7])));
        float n = fminf(fminf(fminf(v[0], v[1]), fminf(v[2], v[3])),
                        fminf(fminf(v[4], v[5]), fminf(v[6], v[7])));
        const bool valid = (gpos0 + s) < nPos;
#pragma unroll
        for (int k = 0; k < 8; k++)
            if (valid && v[k] == m) cmax[k] += m;
#pragma unroll
        for (int k = 0; k < 4; k++)
            if (valid && v[k] == n) clo += (1u << (8 * k));
#pragma unroll
        for (int k = 4; k < 8; k++)
            if (valid && v[k] == n) chi += (1u << (8 * (k - 4)));
    }
}

template <int HALO_T, int LOG_NDI, int MINB, int HAS_D1>
__global__ __launch_bounds__(NTHR, MINB)
void hydra_kernel(const float* __restrict__ X, const float* __restrict__ W,
                  const int* __restrict__ I, float* __restrict__ out, int diBase)
{
    extern __shared__ float sm[];
    float2*       Wsh = (float2*)sm;
    float*        A   = sm + 160;              // [0, HALO) halo | [HALO, HALO+8192) | halo
    float4*       A4  = (float4*)A;
    const float2* A2  = (const float2*)A;

    constexpr int NFL = 2 * HALO_T + 8192;     // signal floats incl. halos
    constexpr int H2  = HALO_T / 2;            // interior start in float2 units

    const int bid = blockIdx.x;
    const int g   = bid & 31;
    const int j   = (bid >> 5) & 1;
    const int di  = diBase + ((bid >> 6) & ((1 << LOG_NDI) - 1));
    const int b   = bid >> (6 + LOG_NDI);
    const int d   = 1 << di;
    const int tid = threadIdx.x;

    // ---- zero signal buffer (halos + interior) ----
#pragma unroll 4
    for (int i = tid; i < NFL / 4; i += NTHR) A4[i] = make_float4(0.f, 0.f, 0.f, 0.f);

    // ---- weights -> smem, pre-duplicated for f32x2 ----
    const float* Wb = W + ((di * 2 + j) * 256 + g * 8) * 9;
    if (tid < 72) { float w = __ldg(Wb + tid); Wsh[tid] = make_float2(w, w); }

    const int* Ib = I + ((di * 2 + j) * 32 + g) * 6;
    const int ic0 = Ib[0], ic1 = Ib[1], ic2 = Ib[2], ic3 = Ib[3], ic4 = Ib[4], ic5 = Ib[5];

    __syncthreads();

    // ---- channel-gather sum into interior ----
    const float4* X4 = (const float4*)X;
    const int rb = b * 12 * 2048;
#pragma unroll 2
    for (int t = tid; t < 2048; t += NTHR) {
        float4 s = X4[rb + ic0 * 2048 + t];
        float4 v;
        v = X4[rb + ic1 * 2048 + t]; s.x += v.x; s.y += v.y; s.z += v.z; s.w += v.w;
        v = X4[rb + ic2 * 2048 + t]; s.x += v.x; s.y += v.y; s.z += v.z; s.w += v.w;
        v = X4[rb + ic3 * 2048 + t]; s.x += v.x; s.y += v.y; s.z += v.z; s.w += v.w;
        v = X4[rb + ic4 * 2048 + t]; s.x += v.x; s.y += v.y; s.z += v.z; s.w += v.w;
        v = X4[rb + ic5 * 2048 + t]; s.x += v.x; s.y += v.y; s.z += v.z; s.w += v.w;
        A4[HALO_T / 4 + t] = s;
    }
    __syncthreads();

    // ---- j==1: in-place first difference, 2 barriers total ----
    int nPos = 8192;
    if (j == 1) {
        nPos = 8191;
        const int cbase = HALO_T + tid * 64;
        const float bnd = A[cbase + 64];       // tid==127 reads right-halo zero
        __syncthreads();
        float4* C4 = (float4*)(A + cbase);
        float4 v = C4[0];
#pragma unroll
        for (int i4 = 0; i4 < 16; i4++) {
            float4 vn;
            if (i4 < 15) vn = C4[i4 + 1];
            else         vn = make_float4(bnd, 0.f, 0.f, 0.f);
            float4 o;
            o.x = v.y - v.x; o.y = v.z - v.y; o.z = v.w - v.z; o.w = vn.x - v.w;
            C4[i4] = o;
            v = vn;
        }
        if (tid == NTHR - 1) A[HALO_T + 8191] = 0.f;
        __syncthreads();
    }

    // ---- main loop: 16 tiles x 2 pairs/thread ----
    float cmax[8];
    unsigned clo = 0u, chi = 0u;
#pragma unroll
    for (int k = 0; k < 8; k++) cmax[k] = 0.f;

    if (!HAS_D1 || d > 1) {
        const int hd = d >> 1;
#pragma unroll 1
        for (int t = 0; t < 16; t++) {
            const int pbase = t * 256 + tid;   // pairs pbase, pbase+128
            float2 z[16];
#pragma unroll
            for (int i = 0; i < 16; i++) z[i] = make_float2(0.f, 0.f);
#pragma unroll
            for (int r = 0; r < 9; r++) {
                const int off = (r - 4) * hd;
                float2 w8[8];
#pragma unroll
                for (int k = 0; k < 8; k++) w8[k] = Wsh[k * 9 + r];
                const float2 x0 = A2[H2 + pbase + off];
                const float2 x1 = A2[H2 + pbase + 128 + off];
#pragma unroll
                for (int k = 0; k < 8; k++) {
                    z[k]     = ffma2(w8[k], x0, z[k]);
                    z[8 + k] = ffma2(w8[k], x1, z[8 + k]);
                }
            }
            epi_pair(z,     2 * pbase,         nPos, cmax, clo, chi);
            epi_pair(z + 8, 2 * (pbase + 128), nPos, cmax, clo, chi);
        }
    } else {
#pragma unroll 1
        for (int t = 0; t < 16; t++) {
            const int pbase = t * 256 + tid;
            float2 z[16];
#pragma unroll
            for (int i = 0; i < 16; i++) z[i] = make_float2(0.f, 0.f);
#pragma unroll
            for (int r = 0; r < 9; r++) {
                float2 w8[8];
#pragma unroll
                for (int k = 0; k < 8; k++) w8[k] = Wsh[k * 9 + r];
                const int ix0 = HALO_T + 2 * pbase + (r - 4);
                const int ix1 = ix0 + 256;
                const float2 x0 = make_float2(A[ix0], A[ix0 + 1]);
                const float2 x1 = make_float2(A[ix1], A[ix1 + 1]);
#pragma unroll
                for (int k = 0; k < 8; k++) {
                    z[k]     = ffma2(w8[k], x0, z[k]);
                    z[8 + k] = ffma2(w8[k], x1, z[8 + k]);
                }
            }
            epi_pair(z,     2 * pbase,         nPos, cmax, clo, chi);
            epi_pair(z + 8, 2 * (pbase + 128), nPos, cmax, clo, chi);
        }
    }

    // ---- block reduction (A reused as scratch) ----
    __syncthreads();
    if (tid < 16) ((unsigned*)A)[tid] = 0u;
    __syncthreads();

    const int lane = tid & 31;
#pragma unroll
    for (int k = 0; k < 8; k++) {
        float v = cmax[k];
        int   c = (int)((k < 4 ? (clo >> (8 * k)) : (chi >> (8 * (k - 4)))) & 0xFFu);
#pragma unroll
        for (int off = 16; off; off >>= 1) {
            v += __shfl_down_sync(0xffffffffu, v, off);
            c += __shfl_down_sync(0xffffffffu, c, off);
        }
        if (lane == 0) {
            atomicAdd(&A[k], v);
            atomicAdd((int*)A + 8 + k, c);
        }
    }
    __syncthreads();

    const int rowBase = ((di * 2 + j) * 2) * 32 + g;
    if (tid < 8) {
        float v = A[tid];
        out[(b * 1280 + rowBase) * 8 + tid] = v > 0.f ? v : 0.f;
    } else if (tid < 16) {
        const int k = tid - 8;
        const int c = ((const int*)A)[8 + k];
        out[(b * 1280 + rowBase + 32) * 8 + k] = (float)c;
    }
}

#define SMEM_A ((160 + 2 * 512 + 8192) * 4)    // 37504 B  (di 0..7)
#define SMEM_B ((160 + 2 * 2048 + 8192) * 4)   // 49792 B  (di 8..9)

extern "C" void kernel_launch(void* const* d_in, const int* in_sizes, int n_in,
                              void* d_out, int out_size)
{
    const float* X = (const float*)d_in[0];
    const float* W = (const float*)d_in[1];
    const int*   I = (const int*)d_in[2];
    float*       O = (float*)d_out;

    static int once = 0;
    if (!once) {
        cudaFuncSetAttribute((const void*)hydra_kernel<512, 3, 5, 1>,
                             cudaFuncAttributeMaxDynamicSharedMemorySize, SMEM_A);
        cudaFuncSetAttribute((const void*)hydra_kernel<2048, 1, 4, 0>,
                             cudaFuncAttributeMaxDynamicSharedMemorySize, SMEM_B);
        once = 1;
    }

    // di 0..7 : 32 batch * 8 di * 2 j * 32 g = 16384 blocks, halo 512
    hydra_kernel<512, 3, 5, 1><<<16384, NTHR, SMEM_A>>>(X, W, I, O, 0);
    // di 8..9 : 32 * 2 * 2 * 32 = 4096 blocks, halo 2048
    hydra_kernel<2048, 1, 4, 0><<<4096, NTHR, SMEM_B>>>(X, W, I, O, 8);
}

// round 4
// speedup vs baseline: 1.4957x; 1.4957x over previous
#include <cuda_runtime.h>

#define NTHR 128
#define HALO 2048
#define SMEM_BYTES ((160 + 2 * HALO + 8192) * 4)   // 49792 B

__device__ __forceinline__ float2 ffma2(float2 a, float2 b, float2 c) {
    float2 d;
    asm("fma.rn.f32x2 %0, %1, %2, %3;"
        : "=l"(reinterpret_cast<unsigned long long&>(d))
        : "l"(reinterpret_cast<unsigned long long&>(a)),
          "l"(reinterpret_cast<unsigned long long&>(b)),
          "l"(reinterpret_cast<unsigned long long&>(c)));
    return d;
}

// epilogue for one position-pair (s=0 always valid, s=1 gated by v1ok)
__device__ __forceinline__ void epi_pair(const float2 z[8], bool v1ok,
                                         float cmax[8], unsigned& clo, unsigned& chi)
{
#pragma unroll
    for (int s = 0; s < 2; s++) {
        float v[8];
#pragma unroll
        for (int k = 0; k < 8; k++) v[k] = s ? z[k].y : z[k].x;
        float m = fmaxf(fmaxf(fmaxf(v[0], v[1]), fmaxf(v[2], v[3])),
                        fmaxf(fmaxf(v[4], v[5]), fmaxf(v[6], v[7])));
        float n = fminf(fminf(fminf(v[0], v[1]), fminf(v[2], v[3])),
                        fminf(fminf(v[4], v[5]), fminf(v[6], v[7])));
        const bool valid = (s == 0) | v1ok;
#pragma unroll
        for (int k = 0; k < 8; k++)
            if (valid && v[k] == m) cmax[k] += m;
#pragma unroll
        for (int k = 0; k < 4; k++)
            if (valid && v[k] == n) clo += (1u << (8 * k));
#pragma unroll
        for (int k = 4; k < 8; k++)
            if (valid && v[k] == n) chi += (1u << (8 * (k - 4)));
    }
}

__global__ __launch_bounds__(NTHR, 2)
void hydra_kernel(const float* __restrict__ X, const float* __restrict__ W,
                  const int* __restrict__ I, float* __restrict__ out)
{
    extern __shared__ float sm[];
    float*        A  = sm + 160;
    float4*       A4 = (float4*)A;
    const float2* A2 = (const float2*)A;

    const int bid = blockIdx.x;
    const int g   = bid & 31;
    const int j   = (bid >> 5) & 1;
    const int di  = (bid >> 6) % 10;
    const int b   = bid / 640;
    const int d   = 1 << di;
    const int tid = threadIdx.x;

    // ---- zero signal buffer (halos + interior): 12288 floats ----
#pragma unroll 4
    for (int i = tid; i < 3072; i += NTHR) A4[i] = make_float4(0.f, 0.f, 0.f, 0.f);

    // ---- weights -> registers, pre-duplicated for f32x2 ----
    const float* Wb = W + ((di * 2 + j) * 256 + g * 8) * 9;
    float2 wp[72];
#pragma unroll
    for (int i = 0; i < 72; i++) { float w = __ldg(Wb + i); wp[i] = make_float2(w, w); }

    const int* Ib = I + ((di * 2 + j) * 32 + g) * 6;
    const int ic0 = Ib[0], ic1 = Ib[1], ic2 = Ib[2], ic3 = Ib[3], ic4 = Ib[4], ic5 = Ib[5];

    __syncthreads();

    // ---- channel-gather sum into interior [HALO, HALO+8192) ----
    const float4* X4 = (const float4*)X;
    const int rb = b * 12 * 2048;
#pragma unroll 2
    for (int t = tid; t < 2048; t += NTHR) {
        float4 s = X4[rb + ic0 * 2048 + t];
        float4 v;
        v = X4[rb + ic1 * 2048 + t]; s.x += v.x; s.y += v.y; s.z += v.z; s.w += v.w;
        v = X4[rb + ic2 * 2048 + t]; s.x += v.x; s.y += v.y; s.z += v.z; s.w += v.w;
        v = X4[rb + ic3 * 2048 + t]; s.x += v.x; s.y += v.y; s.z += v.z; s.w += v.w;
        v = X4[rb + ic4 * 2048 + t]; s.x += v.x; s.y += v.y; s.z += v.z; s.w += v.w;
        v = X4[rb + ic5 * 2048 + t]; s.x += v.x; s.y += v.y; s.z += v.z; s.w += v.w;
        A4[HALO / 4 + t] = s;
    }
    __syncthreads();

    // ---- j==1: in-place first difference, 2 barriers ----
    int nPos = 8192;
    if (j == 1) {
        nPos = 8191;
        const int cbase = HALO + tid * 64;
        const float bnd = A[cbase + 64];       // tid==127 reads right-halo zero
        __syncthreads();
        float4* C4 = (float4*)(A + cbase);
        float4 v = C4[0];
#pragma unroll
        for (int i4 = 0; i4 < 16; i4++) {
            float4 vn;
            if (i4 < 15) vn = C4[i4 + 1];
            else         vn = make_float4(bnd, 0.f, 0.f, 0.f);
            float4 o;
            o.x = v.y - v.x; o.y = v.z - v.y; o.z = v.w - v.z; o.w = vn.x - v.w;
            C4[i4] = o;
            v = vn;
        }
        if (tid == NTHR - 1) A[HALO + 8191] = 0.f;
        __syncthreads();
    }

    // ---- main loop: 32 iterations x 1 pair/thread, weights in regs ----
    float cmax[8];
    unsigned clo = 0u, chi = 0u;
#pragma unroll
    for (int k = 0; k < 8; k++) cmax[k] = 0.f;

    if (d == 1) {
#pragma unroll 1
        for (int t = 0; t < 32; t++) {
            const int p = t * 128 + tid;
            float2 v0 = A2[1022 + p], v1 = A2[1023 + p], v2 = A2[1024 + p],
                   v3 = A2[1025 + p], v4 = A2[1026 + p];
            float2 xv[9];
            xv[0] = v0; xv[2] = v1; xv[4] = v2; xv[6] = v3; xv[8] = v4;
            xv[1] = make_float2(v0.y, v1.x);
            xv[3] = make_float2(v1.y, v2.x);
            xv[5] = make_float2(v2.y, v3.x);
            xv[7] = make_float2(v3.y, v4.x);
            float2 z[8];
#pragma unroll
            for (int k = 0; k < 8; k++) z[k] = make_float2(0.f, 0.f);
#pragma unroll
            for (int r = 0; r < 9; r++) {
                const float2 x2 = xv[r];
#pragma unroll
                for (int k = 0; k < 8; k++) z[k] = ffma2(wp[k * 9 + r], x2, z[k]);
            }
            epi_pair(z, (2 * p + 1) < nPos, cmax, clo, chi);
        }
    } else {
        const int hd = d >> 1;
#pragma unroll 1
        for (int t = 0; t < 32; t++) {
            const int p = t * 128 + tid;
            float2 z[8];
#pragma unroll
            for (int k = 0; k < 8; k++) z[k] = make_float2(0.f, 0.f);
#pragma unroll
            for (int r = 0; r < 9; r++) {
                const float2 x2 = A2[1024 + p + (r - 4) * hd];
#pragma unroll
                for (int k = 0; k < 8; k++) z[k] = ffma2(wp[k * 9 + r], x2, z[k]);
            }
            epi_pair(z, (2 * p + 1) < nPos, cmax, clo, chi);
        }
    }

    // ---- block reduction (A reused as scratch) ----
    __syncthreads();
    if (tid < 16) ((unsigned*)A)[tid] = 0u;
    __syncthreads();

    const int lane = tid & 31;
#pragma unroll
    for (int k = 0; k < 8; k++) {
        float v = cmax[k];
        int   c = (int)((k < 4 ? (clo >> (8 * k)) : (chi >> (8 * (k - 4)))) & 0xFFu);
#pragma unroll
        for (int off = 16; off; off >>= 1) {
            v += __shfl_down_sync(0xffffffffu, v, off);
            c += __shfl_down_sync(0xffffffffu, c, off);
        }
        if (lane == 0) {
            atomicAdd(&A[k], v);
            atomicAdd((int*)A + 8 + k, c);
        }
    }
    __syncthreads();

    // ---- outputs ----
    const int rowBase = ((di * 2 + j) * 2) * 32 + g;
    if (tid < 8) {
        float v = A[tid];
        out[(b * 1280 + rowBase) * 8 + tid] = v > 0.f ? v : 0.f;
    } else if (tid < 16) {
        const int k = tid - 8;
        const int c = ((const int*)A)[8 + k];
        out[(b * 1280 + rowBase + 32) * 8 + k] = (float)c;
    }
}

extern "C" void kernel_launch(void* const* d_in, const int* in_sizes, int n_in,
                              void* d_out, int out_size)
{
    const float* X = (const float*)d_in[0];
    const float* W = (const float*)d_in[1];
    const int*   I = (const int*)d_in[2];
    float*       O = (float*)d_out;

    cudaFuncSetAttribute(hydra_kernel, cudaFuncAttributeMaxDynamicSharedMemorySize, SMEM_BYTES);
    hydra_kernel<<<20480, NTHR, SMEM_BYTES>>>(X, W, I, O);
}

// round 5
// speedup vs baseline: 1.4977x; 1.0014x over previous
#include <cuda_runtime.h>

#define NTHR 128
#define HALO 2048
#define SMEM_BYTES ((160 + 2 * HALO + 8192) * 4)   // 49792 B

__device__ __forceinline__ float2 ffma2(float2 a, float2 b, float2 c) {
    float2 d;
    asm("fma.rn.f32x2 %0, %1, %2, %3;"
        : "=l"(reinterpret_cast<unsigned long long&>(d))
        : "l"(reinterpret_cast<unsigned long long&>(a)),
          "l"(reinterpret_cast<unsigned long long&>(b)),
          "l"(reinterpret_cast<unsigned long long&>(c)));
    return d;
}

// epilogue for one position-pair (s=0 always valid, s=1 gated by v1ok)
__device__ __forceinline__ void epi_pair(const float2 z[8], bool v1ok,
                                         float cmax[8], unsigned& clo, unsigned& chi)
{
#pragma unroll
    for (int s = 0; s < 2; s++) {
        float v[8];
#pragma unroll
        for (int k = 0; k < 8; k++) v[k] = s ? z[k].y : z[k].x;
        float m = fmaxf(fmaxf(fmaxf(v[0], v[1]), fmaxf(v[2], v[3])),
                        fmaxf(fmaxf(v[4], v[5]), fmaxf(v[6], v[7])));
        float n = fminf(fminf(fminf(v[0], v[1]), fminf(v[2], v[3])),
                        fminf(fminf(v[4], v[5]), fminf(v[6], v[7])));
        const bool valid = (s == 0) | v1ok;
#pragma unroll
        for (int k = 0; k < 8; k++)
            if (valid && v[k] == m) cmax[k] += m;
#pragma unroll
        for (int k = 0; k < 4; k++)
            if (valid && v[k] == n) clo += (1u << (8 * k));
#pragma unroll
        for (int k = 4; k < 8; k++)
            if (valid && v[k] == n) chi += (1u << (8 * (k - 4)));
    }
}

__global__ __launch_bounds__(NTHR, 2)
void hydra_kernel(const float* __restrict__ X, const float* __restrict__ W,
                  const int* __restrict__ I, float* __restrict__ out)
{
    extern __shared__ float sm[];
    float*        A  = sm + 160;
    float4*       A4 = (float4*)A;
    const float2* A2 = (const float2*)A;

    const int bid = blockIdx.x;
    const int g   = bid & 31;
    const int j   = (bid >> 5) & 1;
    const int di  = (bid >> 6) % 10;
    const int b   = bid / 640;
    const int d   = 1 << di;
    const int tid = threadIdx.x;

    // ---- zero signal buffer (halos + interior): 12288 floats ----
#pragma unroll 4
    for (int i = tid; i < 3072; i += NTHR) A4[i] = make_float4(0.f, 0.f, 0.f, 0.f);

    // ---- weights -> registers, pre-duplicated for f32x2 ----
    const float* Wb = W + ((di * 2 + j) * 256 + g * 8) * 9;
    float2 wp[72];
#pragma unroll
    for (int i = 0; i < 72; i++) { float w = __ldg(Wb + i); wp[i] = make_float2(w, w); }

    const int* Ib = I + ((di * 2 + j) * 32 + g) * 6;
    const int ic0 = Ib[0], ic1 = Ib[1], ic2 = Ib[2], ic3 = Ib[3], ic4 = Ib[4], ic5 = Ib[5];

    __syncthreads();

    // ---- channel-gather sum into interior [HALO, HALO+8192) ----
    const float4* X4 = (const float4*)X;
    const int rb = b * 12 * 2048;
#pragma unroll 2
    for (int t = tid; t < 2048; t += NTHR) {
        float4 s = X4[rb + ic0 * 2048 + t];
        float4 v;
        v = X4[rb + ic1 * 2048 + t]; s.x += v.x; s.y += v.y; s.z += v.z; s.w += v.w;
        v = X4[rb + ic2 * 2048 + t]; s.x += v.x; s.y += v.y; s.z += v.z; s.w += v.w;
        v = X4[rb + ic3 * 2048 + t]; s.x += v.x; s.y += v.y; s.z += v.z; s.w += v.w;
        v = X4[rb + ic4 * 2048 + t]; s.x += v.x; s.y += v.y; s.z += v.z; s.w += v.w;
        v = X4[rb + ic5 * 2048 + t]; s.x += v.x; s.y += v.y; s.z += v.z; s.w += v.w;
        A4[HALO / 4 + t] = s;
    }
    __syncthreads();

    // ---- j==1: in-place first difference, 2 barriers ----
    int nPos = 8192;
    if (j == 1) {
        nPos = 8191;
        const int cbase = HALO + tid * 64;
        const float bnd = A[cbase + 64];       // tid==127 reads right-halo zero
        __syncthreads();
        float4* C4 = (float4*)(A + cbase);
        float4 v = C4[0];
#pragma unroll
        for (int i4 = 0; i4 < 16; i4++) {
            float4 vn;
            if (i4 < 15) vn = C4[i4 + 1];
            else         vn = make_float4(bnd, 0.f, 0.f, 0.f);
            float4 o;
            o.x = v.y - v.x; o.y = v.z - v.y; o.z = v.w - v.z; o.w = vn.x - v.w;
            C4[i4] = o;
            v = vn;
        }
        if (tid == NTHR - 1) A[HALO + 8191] = 0.f;
        __syncthreads();
    }

    // ---- main loop: 32 iterations x 1 pair/thread, weights in regs ----
    float cmax[8];
    unsigned clo = 0u, chi = 0u;
#pragma unroll
    for (int k = 0; k < 8; k++) cmax[k] = 0.f;

    if (d == 1) {
#pragma unroll 1
        for (int t = 0; t < 32; t++) {
            const int p = t * 128 + tid;
            float2 v0 = A2[1022 + p], v1 = A2[1023 + p], v2 = A2[1024 + p],
                   v3 = A2[1025 + p], v4 = A2[1026 + p];
            float2 xv[9];
            xv[0] = v0; xv[2] = v1; xv[4] = v2; xv[6] = v3; xv[8] = v4;
            xv[1] = make_float2(v0.y, v1.x);
            xv[3] = make_float2(v1.y, v2.x);
            xv[5] = make_float2(v2.y, v3.x);
            xv[7] = make_float2(v3.y, v4.x);
            float2 z[8];
#pragma unroll
            for (int k = 0; k < 8; k++) z[k] = make_float2(0.f, 0.f);
#pragma unroll
            for (int r = 0; r < 9; r++) {
                const float2 x2 = xv[r];
#pragma unroll
                for (int k = 0; k < 8; k++) z[k] = ffma2(wp[k * 9 + r], x2, z[k]);
            }
            epi_pair(z, (2 * p + 1) < nPos, cmax, clo, chi);
        }
    } else {
        const int hd = d >> 1;
#pragma unroll 1
        for (int t = 0; t < 32; t++) {
            const int p = t * 128 + tid;
            float2 z[8];
#pragma unroll
            for (int k = 0; k < 8; k++) z[k] = make_float2(0.f, 0.f);
#pragma unroll
            for (int r = 0; r < 9; r++) {
                const float2 x2 = A2[1024 + p + (r - 4) * hd];
#pragma unroll
                for (int k = 0; k < 8; k++) z[k] = ffma2(wp[k * 9 + r], x2, z[k]);
            }
            epi_pair(z, (2 * p + 1) < nPos, cmax, clo, chi);
        }
    }

    // ---- block reduction (A reused as scratch) ----
    __syncthreads();
    if (tid < 16) ((unsigned*)A)[tid] = 0u;
    __syncthreads();

    const int lane = tid & 31;
#pragma unroll
    for (int k = 0; k < 8; k++) {
        float v = cmax[k];
        int   c = (int)((k < 4 ? (clo >> (8 * k)) : (chi >> (8 * (k - 4)))) & 0xFFu);
#pragma unroll
        for (int off = 16; off; off >>= 1) {
            v += __shfl_down_sync(0xffffffffu, v, off);
            c += __shfl_down_sync(0xffffffffu, c, off);
        }
        if (lane == 0) {
            atomicAdd(&A[k], v);
            atomicAdd((int*)A + 8 + k, c);
        }
    }
    __syncthreads();

    // ---- outputs ----
    const int rowBase = ((di * 2 + j) * 2) * 32 + g;
    if (tid < 8) {
        float v = A[tid];
        out[(b * 1280 + rowBase) * 8 + tid] = v > 0.f ? v : 0.f;
    } else if (tid < 16) {
        const int k = tid - 8;
        const int c = ((const int*)A)[8 + k];
        out[(b * 1280 + rowBase + 32) * 8 + k] = (float)c;
    }
}

extern "C" void kernel_launch(void* const* d_in, const int* in_sizes, int n_in,
                              void* d_out, int out_size)
{
    const float* X = (const float*)d_in[0];
    const float* W = (const float*)d_in[1];
    const int*   I = (const int*)d_in[2];
    float*       O = (float*)d_out;

    cudaFuncSetAttribute(hydra_kernel, cudaFuncAttributeMaxDynamicSharedMemorySize, SMEM_BYTES);
    hydra_kernel<<<20480, NTHR, SMEM_BYTES>>>(X, W, I, O);
}